// round 11
// baseline (speedup 1.0000x reference)
#include <cuda_runtime.h>
#include <cuda_fp16.h>
#include <math.h>
#include <stdint.h>

#define VV 32000
#define DD 512
#define BB 8
#define SS 1024
#define BSZ (BB*SS)          // 8192
#define EPSV 1e-5f
#define NSEG 8
#define SEGLEN (SS/NSEG)     // 128
#define NTILE_N 125          // 256-wide n tiles
#define NTILES (NSEG*NTILE_N*BB)   // 8000

// ---------------- scratch (static device arrays; no cudaMalloc) ----------------
__device__ float  g_f  [(size_t)BSZ*DD];
__device__ float  g_x  [(size_t)BSZ*DD];
__device__ float  g_t  [(size_t)BSZ*DD];
__device__ float  g_xn [(size_t)BSZ*DD];
__device__ __half g_embh[(size_t)BSZ*DD];  // emb fp16 k16-pair-permuted
__device__ __half g_Wh [(size_t)3*DD*DD];  // weights transposed [z][n][k] fp16 permuted
__device__ __half g_xh [(size_t)BSZ*DD];   // final-LN output fp16 permuted
__device__ __half g_Eh [(size_t)VV*DD];    // E fp16 permuted
__device__ int    g_prog[BB];              // completed segments per batch
__device__ int    g_tick;                  // worker ticket counter

// ================= helpers =================
__device__ __forceinline__ float warp_sum(float v) {
    #pragma unroll
    for (int o = 16; o; o >>= 1) v += __shfl_xor_sync(0xffffffffu, v, o);
    return v;
}
__device__ __forceinline__ uint32_t swz(uint32_t byte_off) {
    return byte_off ^ (((byte_off >> 7) & 3u) << 5);
}
__device__ __forceinline__ uint32_t smem_u32(const void* p) {
    uint32_t a;
    asm("{ .reg .u64 t; cvta.to.shared.u64 t, %1; cvt.u32.u64 %0, t; }" : "=r"(a) : "l"(p));
    return a;
}
__device__ __forceinline__ void cp16(uint32_t d, const void* s) {
    asm volatile("cp.async.cg.shared.global [%0], [%1], 16;" :: "r"(d), "l"(s) : "memory");
}
__device__ __forceinline__ void cpcommit() {
    asm volatile("cp.async.commit_group;" ::: "memory");
}
template<int N> __device__ __forceinline__ void cpwait() {
    asm volatile("cp.async.wait_group %0;" :: "n"(N) : "memory");
}
__device__ __forceinline__ void mma16816(float* c, const uint32_t* a, uint32_t b0, uint32_t b1) {
    asm volatile(
        "mma.sync.aligned.m16n8k16.row.col.f32.f16.f16.f32 "
        "{%0,%1,%2,%3}, {%4,%5,%6,%7}, {%8,%9}, {%0,%1,%2,%3};"
        : "+f"(c[0]), "+f"(c[1]), "+f"(c[2]), "+f"(c[3])
        : "r"(a[0]), "r"(a[1]), "r"(a[2]), "r"(a[3]), "r"(b0), "r"(b1));
}
__device__ __forceinline__ void pack_k16(const float* v, uint32_t* w) {
    #pragma unroll
    for (int j = 0; j < 8; j++) {
        int p = (j & 1) ? (4 + (j >> 1)) : (j >> 1);
        __half2 h = __floats2half2_rn(v[2*p], v[2*p+1]);
        w[j] = *(uint32_t*)&h;
    }
}
__device__ __forceinline__ void ldrow16(float* v, const float* p, int lane) {
    const float4* p4 = (const float4*)(p + lane * 16);
    #pragma unroll
    for (int i = 0; i < 4; i++) {
        float4 t = p4[i];
        v[i*4+0] = t.x; v[i*4+1] = t.y; v[i*4+2] = t.z; v[i*4+3] = t.w;
    }
}

// ---------------- 0a. E -> fp16 permuted ----------------
__global__ void k_conv_E(const float* __restrict__ E) {
    int idx = blockIdx.x * blockDim.x + threadIdx.x;
    int n = idx >> 5, blk = idx & 31;
    const float* src = E + (size_t)n * DD + blk * 16;
    float v[16];
    #pragma unroll
    for (int i = 0; i < 4; i++) {
        float4 t = *(const float4*)(src + i * 4);
        v[i*4+0] = t.x; v[i*4+1] = t.y; v[i*4+2] = t.z; v[i*4+3] = t.w;
    }
    uint32_t w[8];
    pack_k16(v, w);
    uint4* dst = (uint4*)((char*)g_Eh + ((size_t)n * DD + blk * 16) * 2);
    dst[0] = make_uint4(w[0], w[1], w[2], w[3]);
    dst[1] = make_uint4(w[4], w[5], w[6], w[7]);
}

// ---------------- 0b. W -> transposed fp16 permuted ----------------
__global__ void k_conv_W(const float* __restrict__ Wih, const float* __restrict__ W1,
                         const float* __restrict__ W2) {
    int t = blockIdx.x * blockDim.x + threadIdx.x;
    int z = t / (DD * 32);
    int rem = t % (DD * 32);
    int n = rem >> 5, blk = rem & 31;
    const float* W = (z == 0) ? Wih : (z == 1) ? W1 : W2;
    float v[16];
    #pragma unroll
    for (int kk = 0; kk < 16; kk++)
        v[kk] = W[(size_t)(blk * 16 + kk) * DD + n];
    uint32_t w[8];
    pack_k16(v, w);
    uint4* dst = (uint4*)((char*)g_Wh + (((size_t)z * DD + n) * DD + blk * 16) * 2);
    dst[0] = make_uint4(w[0], w[1], w[2], w[3]);
    dst[1] = make_uint4(w[4], w[5], w[6], w[7]);
}

// ---------------- 1. embedding gather -> fp16 permuted ----------------
__global__ void k_gather(const int* __restrict__ tokens, const float* __restrict__ E) {
    int row = blockIdx.x * 8 + (threadIdx.x >> 5);
    int lane = threadIdx.x & 31;
    int tok = tokens[row];
    const float* src = E + (size_t)tok * DD + lane * 16;
    float v[16];
    #pragma unroll
    for (int i = 0; i < 4; i++) {
        float4 t = *(const float4*)(src + i * 4);
        v[i*4+0] = t.x; v[i*4+1] = t.y; v[i*4+2] = t.z; v[i*4+3] = t.w;
    }
    uint32_t w[8];
    pack_k16(v, w);
    uint4* dst = (uint4*)((char*)g_embh + ((size_t)row * DD + lane * 16) * 2);
    dst[0] = make_uint4(w[0], w[1], w[2], w[3]);
    dst[1] = make_uint4(w[4], w[5], w[6], w[7]);
}

// ---------------- 2. phase-1 GEMMs via fp16 mma (fused 3x, 128x128 tiles) ------
#define P1_STAGE 32768
#define SMEM_P1 (3*P1_STAGE)
#define NCHUNK 8

__global__ __launch_bounds__(256, 2) void k_p1_mma(
    const float* __restrict__ bh, const float* __restrict__ b1f,
    const float* __restrict__ b2f)
{
    extern __shared__ char smem[];
    const uint32_t sb = smem_u32(smem);
    const int tid = threadIdx.x;
    const int wid = tid >> 5, lane = tid & 31;
    const int g = lane >> 2, t = lane & 3;
    const int warpM = wid >> 2, warpN = wid & 3;
    const int m0 = blockIdx.y * 128;
    const int z = blockIdx.x >> 2;
    const int nloc0 = (blockIdx.x & 3) * 128;
    const float* bias = (z == 0) ? bh : (z == 1) ? b1f : b2f;
    float* Out = (z == 0) ? g_f : (z == 1) ? g_x : g_t;

    float acc[4][4][4];
    #pragma unroll
    for (int mt = 0; mt < 4; mt++)
        #pragma unroll
        for (int nt = 0; nt < 4; nt++)
            #pragma unroll
            for (int i = 0; i < 4; i++) acc[mt][nt][i] = 0.f;

    const char* gA = (const char*)g_embh + (size_t)m0 * DD * 2;
    const char* gB = (const char*)g_Wh + ((size_t)z * DD + nloc0) * DD * 2;

    auto LOAD = [&](int c) {
        uint32_t st = sb + (uint32_t)(c % 3) * P1_STAGE;
        int kb = c * 128;
        #pragma unroll
        for (int it = 0; it < 4; it++) {
            int idx = it * 256 + tid;
            int row = idx >> 3, q = idx & 7;
            uint32_t so = swz((uint32_t)(row * 128 + q * 16));
            cp16(st + so,         gA + (size_t)row * 1024 + kb + q * 16);
            cp16(st + 16384 + so, gB + (size_t)row * 1024 + kb + q * 16);
        }
        cpcommit();
    };
    auto COMP = [&](int buf) {
        const char* sA = smem + buf * P1_STAGE;
        const char* sB = smem + buf * P1_STAGE + 16384;
        #pragma unroll
        for (int kk = 0; kk < 4; kk++) {
            uint32_t a[4][4];
            #pragma unroll
            for (int mt = 0; mt < 4; mt++) {
                int r0 = warpM * 64 + mt * 16 + g;
                uint2 v1 = *(const uint2*)(sA + swz((uint32_t)(r0 * 128 + kk * 32 + t * 8)));
                uint2 v2 = *(const uint2*)(sA + swz((uint32_t)((r0 + 8) * 128 + kk * 32 + t * 8)));
                a[mt][0] = v1.x; a[mt][1] = v2.x; a[mt][2] = v1.y; a[mt][3] = v2.y;
            }
            #pragma unroll
            for (int nt = 0; nt < 4; nt++) {
                int nr = warpN * 32 + nt * 8 + g;
                uint2 bv = *(const uint2*)(sB + swz((uint32_t)(nr * 128 + kk * 32 + t * 8)));
                #pragma unroll
                for (int mt = 0; mt < 4; mt++)
                    mma16816(acc[mt][nt], a[mt], bv.x, bv.y);
            }
        }
    };

    LOAD(0); LOAD(1);
    #pragma unroll 1
    for (int c = 0; c < NCHUNK; c++) {
        if (c < NCHUNK - 1) cpwait<1>(); else cpwait<0>();
        __syncthreads();
        if (c + 2 < NCHUNK) LOAD(c + 2);
        COMP(c % 3);
    }

    #pragma unroll
    for (int mt = 0; mt < 4; mt++) {
        int mrow = m0 + warpM * 64 + mt * 16 + g;
        #pragma unroll
        for (int nt = 0; nt < 4; nt++) {
            int nl = nloc0 + warpN * 32 + nt * 8 + 2 * t;
            float bx = bias[nl], by = bias[nl + 1];
            float2 lo, hi;
            lo.x = acc[mt][nt][0] + bx; lo.y = acc[mt][nt][1] + by;
            hi.x = acc[mt][nt][2] + bx; hi.y = acc[mt][nt][3] + by;
            if (z == 0) {
                lo.x = 1.f/(1.f+expf(-lo.x)); lo.y = 1.f/(1.f+expf(-lo.y));
                hi.x = 1.f/(1.f+expf(-hi.x)); hi.y = 1.f/(1.f+expf(-hi.y));
            }
            *(float2*)(Out + (size_t)mrow * DD + nl) = lo;
            *(float2*)(Out + (size_t)(mrow + 8) * DD + nl) = hi;
        }
    }
}

// ---------------- 3. combine: x = silu(z1)*z2 ; reset pipeline counters ----
__global__ void k_combine() {
    if (blockIdx.x == 0) {
        if (threadIdx.x < BB) g_prog[threadIdx.x] = 0;
        if (threadIdx.x == BB) g_tick = 0;
    }
    size_t i = (size_t)blockIdx.x * blockDim.x + threadIdx.x;
    float4 z1 = ((const float4*)g_x)[i];
    float4 z2 = ((const float4*)g_t)[i];
    float4 r;
    r.x = (z1.x / (1.f + expf(-z1.x))) * z2.x;
    r.y = (z1.y / (1.f + expf(-z1.y))) * z2.y;
    r.z = (z1.z / (1.f + expf(-z1.z))) * z2.z;
    r.w = (z1.w / (1.f + expf(-z1.w))) * z2.w;
    ((float4*)g_x)[i] = r;
}

// ---------------- 4. fused persistent kernel ----------------
// grid = 148 CTAs, 1 per SM (144KB smem). blocks 0..7: scan; 8..147: logits workers.
// Worker: CTA tile 128(M) x 256(N), 8 warps 2Mx4N, warp tile 64x64, 256 regs.
#define W_STAGE 49152          // A 16KB + B 32KB
#define SMEM_W (3*W_STAGE)     // 144KB

__global__ __launch_bounds__(256, 1) void k_fused(
    float* __restrict__ out,
    const float* __restrict__ h0,
    const float* __restrict__ lng, const float* __restrict__ lnb,
    const float* __restrict__ lnfg, const float* __restrict__ lnfb)
{
    extern __shared__ char smem[];
    const int tid = threadIdx.x;
    const int wid = tid >> 5, lane = tid & 31;

    if (blockIdx.x < BB) {
        // ================= scan CTA for batch b =================
        float* ring = (float*)smem;                         // 8 stages x 1024 floats
        volatile int* prog = (volatile int*)(smem + 32768); // [0]=scan steps, [1..7]=finln warps 0-6
        const int b = blockIdx.x;
        if (tid < 16) prog[tid] = 0;
        __syncthreads();

        if (wid == 7) {
            // ---- producer warp ----
            size_t base = (size_t)b * SS * DD;
            auto issue = [&](int s) {
                if (s < SS) {
                    uint32_t dst = smem_u32(ring + (size_t)(s & 7) * 1024);
                    const float* fs = g_f + base + (size_t)s * DD;
                    const float* xs = g_x + base + (size_t)s * DD;
                    #pragma unroll
                    for (int i = 0; i < 4; i++) {
                        int c = i * 32 + lane;
                        cp16(dst + c * 16,        fs + c * 4);
                        cp16(dst + 2048 + c * 16, xs + c * 4);
                    }
                }
                cpcommit();
            };
            #pragma unroll
            for (int p = 0; p < 6; p++) issue(p);

            float h[16], gw[16], gb[16];
            #pragma unroll
            for (int i = 0; i < 4; i++) {
                int off = i * 128 + lane * 4;
                *(float4*)(h  + i*4) = *(const float4*)(h0  + off);
                *(float4*)(gw + i*4) = *(const float4*)(lng + off);
                *(float4*)(gb + i*4) = *(const float4*)(lnb + off);
            }

            cpwait<5>();
            float fc[16], Bv[16];
            #pragma unroll
            for (int i = 0; i < 4; i++) {
                int off = i * 128 + lane * 4;
                float4 fv = *(const float4*)(ring + off);
                float4 xv = *(const float4*)(ring + 512 + off);
                fc[i*4+0]=fv.x; fc[i*4+1]=fv.y; fc[i*4+2]=fv.z; fc[i*4+3]=fv.w;
                Bv[i*4+0]=fmaf(-fv.x,xv.x,xv.x); Bv[i*4+1]=fmaf(-fv.y,xv.y,xv.y);
                Bv[i*4+2]=fmaf(-fv.z,xv.z,xv.z); Bv[i*4+3]=fmaf(-fv.w,xv.w,xv.w);
            }

            #pragma unroll 1
            for (int s = 0; s < SS; s++) {
                float hr[16];
                #pragma unroll
                for (int j = 0; j < 16; j++) hr[j] = fmaf(fc[j], h[j], Bv[j]);

                float p4s[4] = {0,0,0,0}, q4s[4] = {0,0,0,0};
                #pragma unroll
                for (int j = 0; j < 16; j++) {
                    p4s[j & 3] += hr[j];
                    q4s[j & 3] = fmaf(hr[j], hr[j], q4s[j & 3]);
                }
                float sum = (p4s[0] + p4s[1]) + (p4s[2] + p4s[3]);
                float ssq = (q4s[0] + q4s[1]) + (q4s[2] + q4s[3]);
                #pragma unroll
                for (int o = 16; o; o >>= 1) {
                    sum += __shfl_xor_sync(0xffffffffu, sum, o);
                    ssq += __shfl_xor_sync(0xffffffffu, ssq, o);
                }

                issue(s + 6);
                cpwait<5>();
                if (s + 1 < SS) {
                    const float* rg = ring + (size_t)((s + 1) & 7) * 1024;
                    #pragma unroll
                    for (int i = 0; i < 4; i++) {
                        int off = i * 128 + lane * 4;
                        float4 fv = *(const float4*)(rg + off);
                        float4 xv = *(const float4*)(rg + 512 + off);
                        fc[i*4+0]=fv.x; fc[i*4+1]=fv.y; fc[i*4+2]=fv.z; fc[i*4+3]=fv.w;
                        Bv[i*4+0]=fmaf(-fv.x,xv.x,xv.x); Bv[i*4+1]=fmaf(-fv.y,xv.y,xv.y);
                        Bv[i*4+2]=fmaf(-fv.z,xv.z,xv.z); Bv[i*4+3]=fmaf(-fv.w,xv.w,xv.w);
                    }
                }

                float mean = sum * (1.f / DD);
                float var  = fmaf(-mean, mean, ssq * (1.f / DD));
                float rstd = rsqrtf(var + EPSV);
                float t1   = -mean * rstd;
                #pragma unroll
                for (int j = 0; j < 16; j++)
                    h[j] = fmaf(gw[j], fmaf(hr[j], rstd, t1), gb[j] + h[j]);

                float* dst = g_xn + base + (size_t)s * DD;
                #pragma unroll
                for (int i = 0; i < 4; i++)
                    *(float4*)(dst + i * 128 + lane * 4) = *(float4*)(h + i * 4);

                if ((s & 7) == 7) {
                    __threadfence_block();
                    if (lane == 0) prog[0] = s + 1;
                }
            }
        } else {
            // ---- trailing finln consumers: warps 0..6, rows r = wid + 7k ----
            float gwf[16], gbf[16];
            ldrow16(gwf, lnfg, lane);
            ldrow16(gbf, lnfb, lane);
            const int slot = wid + 1;
            for (int r = wid; r < SS; r += 7) {
                if (lane == 0) { while (prog[0] <= r) __nanosleep(40); }
                __syncwarp();
                __threadfence_block();
                const float* p = g_xn + ((size_t)b * SS + r) * DD;
                float v[16];
                ldrow16(v, p, lane);
                float s4[4] = {0,0,0,0}, q4[4] = {0,0,0,0};
                #pragma unroll
                for (int j = 0; j < 16; j++) {
                    s4[j & 3] += v[j];
                    q4[j & 3] = fmaf(v[j], v[j], q4[j & 3]);
                }
                float sum = warp_sum((s4[0] + s4[1]) + (s4[2] + s4[3]));
                float ssq = warp_sum((q4[0] + q4[1]) + (q4[2] + q4[3]));
                float mean = sum * (1.f / DD);
                float var  = ssq * (1.f / DD) - mean * mean;
                float rstd = rsqrtf(var + EPSV);
                #pragma unroll
                for (int j = 0; j < 16; j++)
                    v[j] = fmaf((v[j] - mean) * rstd, gwf[j], gbf[j]);
                uint32_t w[8];
                pack_k16(v, w);
                uint4* dst = (uint4*)((char*)g_xh + (((size_t)b * SS + r) * DD + lane * 16) * 2);
                dst[0] = make_uint4(w[0], w[1], w[2], w[3]);
                dst[1] = make_uint4(w[4], w[5], w[6], w[7]);
                __threadfence();
                if (lane == 0) {
                    prog[slot] = r + 1;
                    int m = prog[1];
                    #pragma unroll
                    for (int i = 2; i < 8; i++) { int pv = prog[i]; m = (pv < m) ? pv : m; }
                    int k = m >> 7;                     // SEGLEN=128
                    if (k > 0) atomicMax(&g_prog[b], k);
                }
                __syncwarp();
            }
            __threadfence();
            if (lane == 0) {
                prog[slot] = SS;
                int m = prog[1];
                #pragma unroll
                for (int i = 2; i < 8; i++) { int pv = prog[i]; m = (pv < m) ? pv : m; }
                atomicMax(&g_prog[b], m >> 7);
            }
        }
        return;
    }

    // ================= persistent logits worker: 128x256 tile, warp 64x64 ========
    __shared__ int s_t;
    const uint32_t sb = smem_u32(smem);
    const int g = lane >> 2, t = lane & 3;
    const int warpM = wid >> 2, warpN = wid & 3;   // warpM in {0,1}, warpN in {0..3}

    for (;;) {
        if (tid == 0) s_t = atomicAdd(&g_tick, 1);
        __syncthreads();
        int tkt = s_t;
        if (tkt >= NTILES) break;
        int seg = tkt / (NTILE_N * BB);
        int rem = tkt % (NTILE_N * BB);
        int b = rem & 7;
        int n0 = (rem >> 3) * 256;
        if (tid == 0) {
            int p;
            for (;;) {
                asm volatile("ld.global.acquire.gpu.s32 %0, [%1];" : "=r"(p) : "l"(&g_prog[b]));
                if (p > seg) break;
                __nanosleep(60);
            }
        }
        __syncthreads();
        const int m0 = b * SS + seg * SEGLEN;

        float acc[4][8][4];
        #pragma unroll
        for (int mt = 0; mt < 4; mt++)
            #pragma unroll
            for (int nt = 0; nt < 8; nt++)
                #pragma unroll
                for (int i = 0; i < 4; i++) acc[mt][nt][i] = 0.f;

        const char* gA = (const char*)g_xh + (size_t)m0 * DD * 2;
        const char* gB = (const char*)g_Eh + (size_t)n0 * DD * 2;

        auto LOAD = [&](int c) {
            uint32_t st = sb + (uint32_t)(c % 3) * W_STAGE;
            int kb = c * 128;
            // A: 128 rows (4 iters), B: 256 rows (8 iters)
            #pragma unroll
            for (int it = 0; it < 4; it++) {
                int idx = it * 256 + tid;
                int row = idx >> 3, q = idx & 7;
                uint32_t so = swz((uint32_t)(row * 128 + q * 16));
                cp16(st + so, gA + (size_t)row * 1024 + kb + q * 16);
            }
            #pragma unroll
            for (int it = 0; it < 8; it++) {
                int idx = it * 256 + tid;
                int row = idx >> 3, q = idx & 7;
                uint32_t so = swz((uint32_t)(row * 128 + q * 16));
                cp16(st + 16384 + so, gB + (size_t)row * 1024 + kb + q * 16);
            }
            cpcommit();
        };
        auto COMP = [&](int buf) {
            const char* sA = smem + buf * W_STAGE;
            const char* sB = smem + buf * W_STAGE + 16384;
            #pragma unroll
            for (int kk = 0; kk < 4; kk++) {
                uint32_t a[4][4];
                #pragma unroll
                for (int mt = 0; mt < 4; mt++) {
                    int r0 = warpM * 64 + mt * 16 + g;
                    uint2 v1 = *(const uint2*)(sA + swz((uint32_t)(r0 * 128 + kk * 32 + t * 8)));
                    uint2 v2 = *(const uint2*)(sA + swz((uint32_t)((r0 + 8) * 128 + kk * 32 + t * 8)));
                    a[mt][0] = v1.x; a[mt][1] = v2.x; a[mt][2] = v1.y; a[mt][3] = v2.y;
                }
                #pragma unroll
                for (int nt = 0; nt < 8; nt++) {
                    int nr = warpN * 64 + nt * 8 + g;
                    uint2 bv = *(const uint2*)(sB + swz((uint32_t)(nr * 128 + kk * 32 + t * 8)));
                    #pragma unroll
                    for (int mt = 0; mt < 4; mt++)
                        mma16816(acc[mt][nt], a[mt], bv.x, bv.y);
                }
            }
        };

        LOAD(0); LOAD(1);
        #pragma unroll 1
        for (int c = 0; c < NCHUNK; c++) {
            if (c < NCHUNK - 1) cpwait<1>(); else cpwait<0>();
            __syncthreads();
            if (c + 2 < NCHUNK) LOAD(c + 2);
            COMP(c % 3);
        }

        #pragma unroll
        for (int mt = 0; mt < 4; mt++) {
            int mrow = m0 + warpM * 64 + mt * 16 + g;
            #pragma unroll
            for (int nt = 0; nt < 8; nt++) {
                int ncol = n0 + warpN * 64 + nt * 8 + 2 * t;
                float2 lo; lo.x = acc[mt][nt][0]; lo.y = acc[mt][nt][1];
                float2 hi; hi.x = acc[mt][nt][2]; hi.y = acc[mt][nt][3];
                *(float2*)(out + (size_t)mrow * VV + ncol) = lo;
                *(float2*)(out + (size_t)(mrow + 8) * VV + ncol) = hi;
            }
        }
        __syncthreads();   // protect smem stages + s_t before next iteration
    }
}

// ---------------- launch ----------------
extern "C" void kernel_launch(void* const* d_in, const int* in_sizes, int n_in,
                              void* d_out, int out_size) {
    const int*   tokens = (const int*)  d_in[0];
    const float* E      = (const float*)d_in[1];
    const float* W_ih   = (const float*)d_in[2];
    const float* b_h    = (const float*)d_in[3];
    const float* W1     = (const float*)d_in[4];
    const float* b1     = (const float*)d_in[5];
    const float* W2     = (const float*)d_in[6];
    const float* b2     = (const float*)d_in[7];
    const float* ln_g   = (const float*)d_in[8];
    const float* ln_b   = (const float*)d_in[9];
    const float* h0     = (const float*)d_in[10];
    const float* lnf_g  = (const float*)d_in[11];
    const float* lnf_b  = (const float*)d_in[12];
    float* out = (float*)d_out;

    static int init_done = 0;
    if (!init_done) {
        cudaFuncSetAttribute(k_p1_mma, cudaFuncAttributeMaxDynamicSharedMemorySize, SMEM_P1);
        cudaFuncSetAttribute(k_fused,  cudaFuncAttributeMaxDynamicSharedMemorySize, SMEM_W);
        init_done = 1;
    }

    k_conv_E<<<(VV*32)/256, 256>>>(E);
    k_conv_W<<<(3*DD*32)/256, 256>>>(W_ih, W1, W2);
    k_gather<<<BSZ/8, 256>>>(tokens, E);
    k_p1_mma<<<dim3(12, 64), 256, SMEM_P1>>>(b_h, b1, b2);
    k_combine<<<4096, 256>>>();
    k_fused<<<148, 256, SMEM_W>>>(out, h0, ln_g, ln_b, lnf_g, lnf_b);
}

// round 12
// speedup vs baseline: 1.0009x; 1.0009x over previous
#include <cuda_runtime.h>
#include <cuda_fp16.h>
#include <math.h>
#include <stdint.h>

#define VV 32000
#define DD 512
#define BB 8
#define SS 1024
#define BSZ (BB*SS)          // 8192
#define EPSV 1e-5f
#define NSEG 8
#define SEGLEN (SS/NSEG)     // 128
#define NTILE_N 250
#define NTILES (NSEG*NTILE_N*BB)   // 16000
#define NWORK 288

// ---------------- scratch (static device arrays; no cudaMalloc) ----------------
__device__ float  g_f  [(size_t)BSZ*DD];
__device__ float  g_x  [(size_t)BSZ*DD];
__device__ float  g_t  [(size_t)BSZ*DD];
__device__ float  g_xn [(size_t)BSZ*DD];
__device__ __half g_embh[(size_t)BSZ*DD];  // emb fp16 k16-pair-permuted
__device__ __half g_Wh [(size_t)3*DD*DD];  // weights transposed [z][n][k] fp16 permuted
__device__ __half g_xh [(size_t)BSZ*DD];   // final-LN output fp16 permuted
__device__ __half g_Eh [(size_t)VV*DD];    // E fp16 permuted
__device__ int    g_prog[BB];              // completed segments per batch
__device__ int    g_tick;                  // worker ticket counter
__device__ int    g_scansm[BB];            // smid of each scan CTA (-1 = unset)
__device__ int    g_convcnt;               // conv_E barrier counter

// ================= helpers =================
__device__ __forceinline__ float warp_sum(float v) {
    #pragma unroll
    for (int o = 16; o; o >>= 1) v += __shfl_xor_sync(0xffffffffu, v, o);
    return v;
}
__device__ __forceinline__ uint32_t swz(uint32_t byte_off) {
    return byte_off ^ (((byte_off >> 7) & 3u) << 5);
}
__device__ __forceinline__ uint32_t smem_u32(const void* p) {
    uint32_t a;
    asm("{ .reg .u64 t; cvta.to.shared.u64 t, %1; cvt.u32.u64 %0, t; }" : "=r"(a) : "l"(p));
    return a;
}
__device__ __forceinline__ void cp16(uint32_t d, const void* s) {
    asm volatile("cp.async.cg.shared.global [%0], [%1], 16;" :: "r"(d), "l"(s) : "memory");
}
__device__ __forceinline__ void cpcommit() {
    asm volatile("cp.async.commit_group;" ::: "memory");
}
template<int N> __device__ __forceinline__ void cpwait() {
    asm volatile("cp.async.wait_group %0;" :: "n"(N) : "memory");
}
__device__ __forceinline__ void mma16816(float* c, const uint32_t* a, uint32_t b0, uint32_t b1) {
    asm volatile(
        "mma.sync.aligned.m16n8k16.row.col.f32.f16.f16.f32 "
        "{%0,%1,%2,%3}, {%4,%5,%6,%7}, {%8,%9}, {%0,%1,%2,%3};"
        : "+f"(c[0]), "+f"(c[1]), "+f"(c[2]), "+f"(c[3])
        : "r"(a[0]), "r"(a[1]), "r"(a[2]), "r"(a[3]), "r"(b0), "r"(b1));
}
__device__ __forceinline__ void pack_k16(const float* v, uint32_t* w) {
    #pragma unroll
    for (int j = 0; j < 8; j++) {
        int p = (j & 1) ? (4 + (j >> 1)) : (j >> 1);
        __half2 h = __floats2half2_rn(v[2*p], v[2*p+1]);
        w[j] = *(uint32_t*)&h;
    }
}
__device__ __forceinline__ void ldrow16(float* v, const float* p, int lane) {
    const float4* p4 = (const float4*)(p + lane * 16);
    #pragma unroll
    for (int i = 0; i < 4; i++) {
        float4 t = p4[i];
        v[i*4+0] = t.x; v[i*4+1] = t.y; v[i*4+2] = t.z; v[i*4+3] = t.w;
    }
}

// ---------------- 1. prep: conv_W (blocks 0-191) + gather (blocks 192-1215) ----
__global__ void k_prep(const int* __restrict__ tokens, const float* __restrict__ E,
                       const float* __restrict__ Wih, const float* __restrict__ W1,
                       const float* __restrict__ W2) {
    int bid = blockIdx.x;
    if (bid < 192) {
        int t = bid * 256 + threadIdx.x;       // over 3*512*32
        int z = t / (DD * 32);
        int rem = t % (DD * 32);
        int n = rem >> 5, blk = rem & 31;
        const float* W = (z == 0) ? Wih : (z == 1) ? W1 : W2;
        float v[16];
        #pragma unroll
        for (int kk = 0; kk < 16; kk++)
            v[kk] = W[(size_t)(blk * 16 + kk) * DD + n];
        uint32_t w[8];
        pack_k16(v, w);
        uint4* dst = (uint4*)((char*)g_Wh + (((size_t)z * DD + n) * DD + blk * 16) * 2);
        dst[0] = make_uint4(w[0], w[1], w[2], w[3]);
        dst[1] = make_uint4(w[4], w[5], w[6], w[7]);
    } else {
        int row = (bid - 192) * 8 + (threadIdx.x >> 5);
        int lane = threadIdx.x & 31;
        int tok = tokens[row];
        const float* src = E + (size_t)tok * DD + lane * 16;
        float v[16];
        #pragma unroll
        for (int i = 0; i < 4; i++) {
            float4 t = *(const float4*)(src + i * 4);
            v[i*4+0] = t.x; v[i*4+1] = t.y; v[i*4+2] = t.z; v[i*4+3] = t.w;
        }
        uint32_t w[8];
        pack_k16(v, w);
        uint4* dst = (uint4*)((char*)g_embh + ((size_t)row * DD + lane * 16) * 2);
        dst[0] = make_uint4(w[0], w[1], w[2], w[3]);
        dst[1] = make_uint4(w[4], w[5], w[6], w[7]);
    }
}

// ---------------- 2. phase-1 GEMMs via fp16 mma (fused 3x, 128x128 tiles) ------
#define STAGE_BYTES 32768
#define SMEM_MMA (3*STAGE_BYTES)
#define NCHUNK 8

__global__ __launch_bounds__(256, 2) void k_p1_mma(
    const float* __restrict__ bh, const float* __restrict__ b1f,
    const float* __restrict__ b2f)
{
    extern __shared__ char smem[];
    const uint32_t sb = smem_u32(smem);
    const int tid = threadIdx.x;
    const int wid = tid >> 5, lane = tid & 31;
    const int g = lane >> 2, t = lane & 3;
    const int warpM = wid >> 2, warpN = wid & 3;
    const int m0 = blockIdx.y * 128;
    const int z = blockIdx.x >> 2;
    const int nloc0 = (blockIdx.x & 3) * 128;
    const float* bias = (z == 0) ? bh : (z == 1) ? b1f : b2f;
    float* Out = (z == 0) ? g_f : (z == 1) ? g_x : g_t;

    float acc[4][4][4];
    #pragma unroll
    for (int mt = 0; mt < 4; mt++)
        #pragma unroll
        for (int nt = 0; nt < 4; nt++)
            #pragma unroll
            for (int i = 0; i < 4; i++) acc[mt][nt][i] = 0.f;

    const char* gA = (const char*)g_embh + (size_t)m0 * DD * 2;
    const char* gB = (const char*)g_Wh + ((size_t)z * DD + nloc0) * DD * 2;

    auto LOAD = [&](int c) {
        uint32_t st = sb + (uint32_t)(c % 3) * STAGE_BYTES;
        int kb = c * 128;
        #pragma unroll
        for (int it = 0; it < 4; it++) {
            int idx = it * 256 + tid;
            int row = idx >> 3, q = idx & 7;
            uint32_t so = swz((uint32_t)(row * 128 + q * 16));
            cp16(st + so,         gA + (size_t)row * 1024 + kb + q * 16);
            cp16(st + 16384 + so, gB + (size_t)row * 1024 + kb + q * 16);
        }
        cpcommit();
    };
    auto COMP = [&](int buf) {
        const char* sA = smem + buf * STAGE_BYTES;
        const char* sB = smem + buf * STAGE_BYTES + 16384;
        #pragma unroll
        for (int kk = 0; kk < 4; kk++) {
            uint32_t a[4][4];
            #pragma unroll
            for (int mt = 0; mt < 4; mt++) {
                int r0 = warpM * 64 + mt * 16 + g;
                uint2 v1 = *(const uint2*)(sA + swz((uint32_t)(r0 * 128 + kk * 32 + t * 8)));
                uint2 v2 = *(const uint2*)(sA + swz((uint32_t)((r0 + 8) * 128 + kk * 32 + t * 8)));
                a[mt][0] = v1.x; a[mt][1] = v2.x; a[mt][2] = v1.y; a[mt][3] = v2.y;
            }
            #pragma unroll
            for (int nt = 0; nt < 4; nt++) {
                int nr = warpN * 32 + nt * 8 + g;
                uint2 bv = *(const uint2*)(sB + swz((uint32_t)(nr * 128 + kk * 32 + t * 8)));
                #pragma unroll
                for (int mt = 0; mt < 4; mt++)
                    mma16816(acc[mt][nt], a[mt], bv.x, bv.y);
            }
        }
    };

    LOAD(0); LOAD(1);
    #pragma unroll 1
    for (int c = 0; c < NCHUNK; c++) {
        if (c < NCHUNK - 1) cpwait<1>(); else cpwait<0>();
        __syncthreads();
        if (c + 2 < NCHUNK) LOAD(c + 2);
        COMP(c % 3);
    }

    #pragma unroll
    for (int mt = 0; mt < 4; mt++) {
        int mrow = m0 + warpM * 64 + mt * 16 + g;
        #pragma unroll
        for (int nt = 0; nt < 4; nt++) {
            int nl = nloc0 + warpN * 32 + nt * 8 + 2 * t;
            float bx = bias[nl], by = bias[nl + 1];
            float2 lo, hi;
            lo.x = acc[mt][nt][0] + bx; lo.y = acc[mt][nt][1] + by;
            hi.x = acc[mt][nt][2] + bx; hi.y = acc[mt][nt][3] + by;
            if (z == 0) {
                lo.x = 1.f/(1.f+expf(-lo.x)); lo.y = 1.f/(1.f+expf(-lo.y));
                hi.x = 1.f/(1.f+expf(-hi.x)); hi.y = 1.f/(1.f+expf(-hi.y));
            }
            *(float2*)(Out + (size_t)mrow * DD + nl) = lo;
            *(float2*)(Out + (size_t)(mrow + 8) * DD + nl) = hi;
        }
    }
}

// ---------------- 3. combine: x = silu(z1)*z2 ; reset pipeline counters ----
__global__ void k_combine() {
    if (blockIdx.x == 0) {
        if (threadIdx.x < BB) { g_prog[threadIdx.x] = 0; g_scansm[threadIdx.x] = -1; }
        if (threadIdx.x == BB) { g_tick = 0; g_convcnt = 0; }
    }
    size_t i = (size_t)blockIdx.x * blockDim.x + threadIdx.x;
    float4 z1 = ((const float4*)g_x)[i];
    float4 z2 = ((const float4*)g_t)[i];
    float4 r;
    r.x = (z1.x / (1.f + expf(-z1.x))) * z2.x;
    r.y = (z1.y / (1.f + expf(-z1.y))) * z2.y;
    r.z = (z1.z / (1.f + expf(-z1.z))) * z2.z;
    r.w = (z1.w / (1.f + expf(-z1.w))) * z2.w;
    ((float4*)g_x)[i] = r;
}

// ---------------- 4. fused persistent kernel ----------------
// blocks 0..7: scan CTA (producer warp 7, finln warps 0-6), then CONVERT to worker.
// blocks 8..295: conv_E chunk -> barrier -> (evict if on scan SM) -> logits worker.
__global__ __launch_bounds__(256, 2) void k_fused(
    float* __restrict__ out,
    const float* __restrict__ E,
    const float* __restrict__ h0,
    const float* __restrict__ lng, const float* __restrict__ lnb,
    const float* __restrict__ lnfg, const float* __restrict__ lnfb)
{
    extern __shared__ char smem[];
    __shared__ int s_t;
    __shared__ int s_flag;
    const int tid = threadIdx.x;
    const int wid = tid >> 5, lane = tid & 31;
    uint32_t mysm;
    asm("mov.u32 %0, %%smid;" : "=r"(mysm));

    if (blockIdx.x < BB) {
        // ================= scan CTA for batch b =================
        float* ring = (float*)smem;                         // 8 stages x 1024 floats
        volatile int* prog = (volatile int*)(smem + 32768); // [0]=scan steps, [1..7]=finln
        const int b = blockIdx.x;
        if (tid == 0) atomicExch(&g_scansm[b], (int)mysm);
        if (tid < 16) prog[tid] = 0;
        __syncthreads();

        if (wid == 7) {
            // ---- producer warp ----
            size_t base = (size_t)b * SS * DD;
            auto issue = [&](int s) {
                if (s < SS) {
                    uint32_t dst = smem_u32(ring + (size_t)(s & 7) * 1024);
                    const float* fs = g_f + base + (size_t)s * DD;
                    const float* xs = g_x + base + (size_t)s * DD;
                    #pragma unroll
                    for (int i = 0; i < 4; i++) {
                        int c = i * 32 + lane;
                        cp16(dst + c * 16,        fs + c * 4);
                        cp16(dst + 2048 + c * 16, xs + c * 4);
                    }
                }
                cpcommit();
            };
            #pragma unroll
            for (int p = 0; p < 6; p++) issue(p);

            float h[16], gw[16], gb[16];
            #pragma unroll
            for (int i = 0; i < 4; i++) {
                int off = i * 128 + lane * 4;
                *(float4*)(h  + i*4) = *(const float4*)(h0  + off);
                *(float4*)(gw + i*4) = *(const float4*)(lng + off);
                *(float4*)(gb + i*4) = *(const float4*)(lnb + off);
            }

            cpwait<5>();
            float fc[16], Bv[16];
            #pragma unroll
            for (int i = 0; i < 4; i++) {
                int off = i * 128 + lane * 4;
                float4 fv = *(const float4*)(ring + off);
                float4 xv = *(const float4*)(ring + 512 + off);
                fc[i*4+0]=fv.x; fc[i*4+1]=fv.y; fc[i*4+2]=fv.z; fc[i*4+3]=fv.w;
                Bv[i*4+0]=fmaf(-fv.x,xv.x,xv.x); Bv[i*4+1]=fmaf(-fv.y,xv.y,xv.y);
                Bv[i*4+2]=fmaf(-fv.z,xv.z,xv.z); Bv[i*4+3]=fmaf(-fv.w,xv.w,xv.w);
            }

            #pragma unroll 1
            for (int s = 0; s < SS; s++) {
                float hr[16];
                #pragma unroll
                for (int j = 0; j < 16; j++) hr[j] = fmaf(fc[j], h[j], Bv[j]);

                float p4s[4] = {0,0,0,0}, q4s[4] = {0,0,0,0};
                #pragma unroll
                for (int j = 0; j < 16; j++) {
                    p4s[j & 3] += hr[j];
                    q4s[j & 3] = fmaf(hr[j], hr[j], q4s[j & 3]);
                }
                float sum = (p4s[0] + p4s[1]) + (p4s[2] + p4s[3]);
                float ssq = (q4s[0] + q4s[1]) + (q4s[2] + q4s[3]);
                #pragma unroll
                for (int o = 16; o; o >>= 1) {
                    sum += __shfl_xor_sync(0xffffffffu, sum, o);
                    ssq += __shfl_xor_sync(0xffffffffu, ssq, o);
                }

                issue(s + 6);
                cpwait<5>();
                if (s + 1 < SS) {
                    const float* rg = ring + (size_t)((s + 1) & 7) * 1024;
                    #pragma unroll
                    for (int i = 0; i < 4; i++) {
                        int off = i * 128 + lane * 4;
                        float4 fv = *(const float4*)(rg + off);
                        float4 xv = *(const float4*)(rg + 512 + off);
                        fc[i*4+0]=fv.x; fc[i*4+1]=fv.y; fc[i*4+2]=fv.z; fc[i*4+3]=fv.w;
                        Bv[i*4+0]=fmaf(-fv.x,xv.x,xv.x); Bv[i*4+1]=fmaf(-fv.y,xv.y,xv.y);
                        Bv[i*4+2]=fmaf(-fv.z,xv.z,xv.z); Bv[i*4+3]=fmaf(-fv.w,xv.w,xv.w);
                    }
                }

                float mean = sum * (1.f / DD);
                float var  = fmaf(-mean, mean, ssq * (1.f / DD));
                float rstd = rsqrtf(var + EPSV);
                float t1   = -mean * rstd;
                #pragma unroll
                for (int j = 0; j < 16; j++)
                    h[j] = fmaf(gw[j], fmaf(hr[j], rstd, t1), gb[j] + h[j]);

                float* dst = g_xn + base + (size_t)s * DD;
                #pragma unroll
                for (int i = 0; i < 4; i++)
                    *(float4*)(dst + i * 128 + lane * 4) = *(float4*)(h + i * 4);

                if ((s & 7) == 7) {
                    __threadfence_block();
                    if (lane == 0) prog[0] = s + 1;
                }
            }
        } else {
            // ---- trailing finln consumers: warps 0..6, rows r = wid + 7k ----
            float gwf[16], gbf[16];
            ldrow16(gwf, lnfg, lane);
            ldrow16(gbf, lnfb, lane);
            const int slot = wid + 1;
            for (int r = wid; r < SS; r += 7) {
                if (lane == 0) { while (prog[0] <= r) __nanosleep(40); }
                __syncwarp();
                __threadfence_block();
                const float* p = g_xn + ((size_t)b * SS + r) * DD;
                float v[16];
                ldrow16(v, p, lane);
                float s4[4] = {0,0,0,0}, q4[4] = {0,0,0,0};
                #pragma unroll
                for (int j = 0; j < 16; j++) {
                    s4[j & 3] += v[j];
                    q4[j & 3] = fmaf(v[j], v[j], q4[j & 3]);
                }
                float sum = warp_sum((s4[0] + s4[1]) + (s4[2] + s4[3]));
                float ssq = warp_sum((q4[0] + q4[1]) + (q4[2] + q4[3]));
                float mean = sum * (1.f / DD);
                float var  = ssq * (1.f / DD) - mean * mean;
                float rstd = rsqrtf(var + EPSV);
                #pragma unroll
                for (int j = 0; j < 16; j++)
                    v[j] = fmaf((v[j] - mean) * rstd, gwf[j], gbf[j]);
                uint32_t w[8];
                pack_k16(v, w);
                uint4* dst = (uint4*)((char*)g_xh + (((size_t)b * SS + r) * DD + lane * 16) * 2);
                dst[0] = make_uint4(w[0], w[1], w[2], w[3]);
                dst[1] = make_uint4(w[4], w[5], w[6], w[7]);
                __threadfence();
                if (lane == 0) {
                    prog[slot] = r + 1;
                    int m = prog[1];
                    #pragma unroll
                    for (int i = 2; i < 8; i++) { int pv = prog[i]; m = (pv < m) ? pv : m; }
                    int k = m >> 7;                     // SEGLEN=128
                    if (k > 0) atomicMax(&g_prog[b], k);
                }
                __syncwarp();
            }
            __threadfence();
            if (lane == 0) {
                prog[slot] = SS;
                int m = prog[1];
                #pragma unroll
                for (int i = 2; i < 8; i++) { int pv = prog[i]; m = (pv < m) ? pv : m; }
                atomicMax(&g_prog[b], m >> 7);
            }
        }
        // ---- CONVERT to logits worker: wait for conv_E completion (instant) ----
        __syncthreads();
        if (tid == 0) {
            int c;
            for (;;) {
                asm volatile("ld.global.acquire.gpu.s32 %0, [%1];" : "=r"(c) : "l"(&g_convcnt));
                if (c >= NWORK) break;
                __nanosleep(100);
            }
            s_flag = 0;
        }
        __syncthreads();
    } else {
        // ================= worker prologue: conv_E chunk + barrier ==============
        int start = (blockIdx.x - BB) * 256 + tid;
        #pragma unroll 1
        for (int idx = start; idx < VV * 32; idx += NWORK * 256) {
            int n = idx >> 5, blk = idx & 31;
            const float* src = E + (size_t)n * DD + blk * 16;
            float v[16];
            #pragma unroll
            for (int i = 0; i < 4; i++) {
                float4 t = *(const float4*)(src + i * 4);
                v[i*4+0] = t.x; v[i*4+1] = t.y; v[i*4+2] = t.z; v[i*4+3] = t.w;
            }
            uint32_t w[8];
            pack_k16(v, w);
            uint4* dst = (uint4*)((char*)g_Eh + ((size_t)n * DD + blk * 16) * 2);
            dst[0] = make_uint4(w[0], w[1], w[2], w[3]);
            dst[1] = make_uint4(w[4], w[5], w[6], w[7]);
        }
        __threadfence();
        __syncthreads();
        if (tid == 0) {
            atomicAdd(&g_convcnt, 1);
            int c;
            for (;;) {
                asm volatile("ld.global.acquire.gpu.s32 %0, [%1];" : "=r"(c) : "l"(&g_convcnt));
                if (c >= NWORK) break;
                __nanosleep(60);
            }
            // eviction: exit if co-resident with a scan CTA
            int ev = 0;
            #pragma unroll 1
            for (int i = 0; i < BB; i++) {
                int v;
                do { v = atomicAdd(&g_scansm[i], 0); if (v < 0) __nanosleep(20); } while (v < 0);
                if ((uint32_t)v == mysm) ev = 1;
            }
            s_flag = ev;
        }
        __syncthreads();
        if (s_flag) return;
    }

    // ================= persistent logits worker =================
    const uint32_t sb = smem_u32(smem);
    const int g = lane >> 2, t = lane & 3;
    const int warpM = wid >> 2, warpN = wid & 3;

    for (;;) {
        if (tid == 0) s_t = atomicAdd(&g_tick, 1);
        __syncthreads();
        int tkt = s_t;
        if (tkt >= NTILES) break;
        int seg = tkt / (NTILE_N * BB);
        int rem = tkt % (NTILE_N * BB);
        int b = rem & 7;
        int n0 = (rem >> 3) * 128;
        if (tid == 0) {
            int p;
            for (;;) {
                asm volatile("ld.global.acquire.gpu.s32 %0, [%1];" : "=r"(p) : "l"(&g_prog[b]));
                if (p > seg) break;
                __nanosleep(60);
            }
        }
        __syncthreads();
        const int m0 = b * SS + seg * SEGLEN;

        float acc[4][4][4];
        #pragma unroll
        for (int mt = 0; mt < 4; mt++)
            #pragma unroll
            for (int nt = 0; nt < 4; nt++)
                #pragma unroll
                for (int i = 0; i < 4; i++) acc[mt][nt][i] = 0.f;

        const char* gA = (const char*)g_xh + (size_t)m0 * DD * 2;
        const char* gB = (const char*)g_Eh + (size_t)n0 * DD * 2;

        auto LOAD = [&](int c) {
            uint32_t st = sb + (uint32_t)(c % 3) * STAGE_BYTES;
            int kb = c * 128;
            #pragma unroll
            for (int it = 0; it < 4; it++) {
                int idx = it * 256 + tid;
                int row = idx >> 3, q = idx & 7;
                uint32_t so = swz((uint32_t)(row * 128 + q * 16));
                cp16(st + so,         gA + (size_t)row * 1024 + kb + q * 16);
                cp16(st + 16384 + so, gB + (size_t)row * 1024 + kb + q * 16);
            }
            cpcommit();
        };
        auto COMP = [&](int buf) {
            const char* sA = smem + buf * STAGE_BYTES;
            const char* sB = smem + buf * STAGE_BYTES + 16384;
            #pragma unroll
            for (int kk = 0; kk < 4; kk++) {
                uint32_t a[4][4];
                #pragma unroll
                for (int mt = 0; mt < 4; mt++) {
                    int r0 = warpM * 64 + mt * 16 + g;
                    uint2 v1 = *(const uint2*)(sA + swz((uint32_t)(r0 * 128 + kk * 32 + t * 8)));
                    uint2 v2 = *(const uint2*)(sA + swz((uint32_t)((r0 + 8) * 128 + kk * 32 + t * 8)));
                    a[mt][0] = v1.x; a[mt][1] = v2.x; a[mt][2] = v1.y; a[mt][3] = v2.y;
                }
                #pragma unroll
                for (int nt = 0; nt < 4; nt++) {
                    int nr = warpN * 32 + nt * 8 + g;
                    uint2 bv = *(const uint2*)(sB + swz((uint32_t)(nr * 128 + kk * 32 + t * 8)));
                    #pragma unroll
                    for (int mt = 0; mt < 4; mt++)
                        mma16816(acc[mt][nt], a[mt], bv.x, bv.y);
                }
            }
        };

        LOAD(0); LOAD(1);
        #pragma unroll 1
        for (int c = 0; c < NCHUNK; c++) {
            if (c < NCHUNK - 1) cpwait<1>(); else cpwait<0>();
            __syncthreads();
            if (c + 2 < NCHUNK) LOAD(c + 2);
            COMP(c % 3);
        }

        #pragma unroll
        for (int mt = 0; mt < 4; mt++) {
            int mrow = m0 + warpM * 64 + mt * 16 + g;
            #pragma unroll
            for (int nt = 0; nt < 4; nt++) {
                int ncol = n0 + warpN * 32 + nt * 8 + 2 * t;
                float2 lo; lo.x = acc[mt][nt][0]; lo.y = acc[mt][nt][1];
                float2 hi; hi.x = acc[mt][nt][2]; hi.y = acc[mt][nt][3];
                *(float2*)(out + (size_t)mrow * VV + ncol) = lo;
                *(float2*)(out + (size_t)(mrow + 8) * VV + ncol) = hi;
            }
        }
        __syncthreads();   // protect smem stages + s_t before next iteration
    }
}

// ---------------- launch ----------------
extern "C" void kernel_launch(void* const* d_in, const int* in_sizes, int n_in,
                              void* d_out, int out_size) {
    const int*   tokens = (const int*)  d_in[0];
    const float* E      = (const float*)d_in[1];
    const float* W_ih   = (const float*)d_in[2];
    const float* b_h    = (const float*)d_in[3];
    const float* W1     = (const float*)d_in[4];
    const float* b1     = (const float*)d_in[5];
    const float* W2     = (const float*)d_in[6];
    const float* b2     = (const float*)d_in[7];
    const float* ln_g   = (const float*)d_in[8];
    const float* ln_b   = (const float*)d_in[9];
    const float* h0     = (const float*)d_in[10];
    const float* lnf_g  = (const float*)d_in[11];
    const float* lnf_b  = (const float*)d_in[12];
    float* out = (float*)d_out;

    static int init_done = 0;
    if (!init_done) {
        cudaFuncSetAttribute(k_p1_mma, cudaFuncAttributeMaxDynamicSharedMemorySize, SMEM_MMA);
        cudaFuncSetAttribute(k_fused,  cudaFuncAttributeMaxDynamicSharedMemorySize, SMEM_MMA);
        init_done = 1;
    }

    k_prep<<<192 + BSZ/8, 256>>>(tokens, E, W_ih, W1, W2);
    k_p1_mma<<<dim3(12, 64), 256, SMEM_MMA>>>(b_h, b1, b2);
    k_combine<<<4096, 256>>>();
    k_fused<<<BB + NWORK, 256, SMEM_MMA>>>(out, E, h0, ln_g, ln_b, lnf_g, lnf_b);
}

// round 13
// speedup vs baseline: 1.0681x; 1.0671x over previous
#include <cuda_runtime.h>
#include <cuda_fp16.h>
#include <math.h>
#include <stdint.h>

#define VV 32000
#define DD 512
#define BB 8
#define SS 1024
#define BSZ (BB*SS)          // 8192
#define EPSV 1e-5f
#define NSEG 8
#define SEGLEN (SS/NSEG)     // 128
#define NTILE_N 250
#define NTILES (NSEG*NTILE_N*BB)   // 16000

// ---------------- scratch (static device arrays; no cudaMalloc) ----------------
__device__ float  g_f  [(size_t)BSZ*DD];
__device__ float  g_x  [(size_t)BSZ*DD];
__device__ float  g_t  [(size_t)BSZ*DD];
__device__ float  g_xn [(size_t)BSZ*DD];
__device__ __half g_embh[(size_t)BSZ*DD];
__device__ __half g_Wh [(size_t)3*DD*DD];
__device__ __half g_xh [(size_t)BSZ*DD];
__device__ __half g_Eh [(size_t)VV*DD];
__device__ int    g_prog[BB];
__device__ int    g_tick;
__device__ int    g_scansm[BB];

// ================= helpers =================
__device__ __forceinline__ float warp_sum(float v) {
    #pragma unroll
    for (int o = 16; o; o >>= 1) v += __shfl_xor_sync(0xffffffffu, v, o);
    return v;
}
__device__ __forceinline__ uint32_t swz(uint32_t byte_off) {
    return byte_off ^ (((byte_off >> 7) & 3u) << 5);
}
__device__ __forceinline__ uint32_t smem_u32(const void* p) {
    uint32_t a;
    asm("{ .reg .u64 t; cvta.to.shared.u64 t, %1; cvt.u32.u64 %0, t; }" : "=r"(a) : "l"(p));
    return a;
}
__device__ __forceinline__ void cp16(uint32_t d, const void* s) {
    asm volatile("cp.async.cg.shared.global [%0], [%1], 16;" :: "r"(d), "l"(s) : "memory");
}
__device__ __forceinline__ void cpcommit() {
    asm volatile("cp.async.commit_group;" ::: "memory");
}
template<int N> __device__ __forceinline__ void cpwait() {
    asm volatile("cp.async.wait_group %0;" :: "n"(N) : "memory");
}
__device__ __forceinline__ void mma16816(float* c, const uint32_t* a, uint32_t b0, uint32_t b1) {
    asm volatile(
        "mma.sync.aligned.m16n8k16.row.col.f32.f16.f16.f32 "
        "{%0,%1,%2,%3}, {%4,%5,%6,%7}, {%8,%9}, {%0,%1,%2,%3};"
        : "+f"(c[0]), "+f"(c[1]), "+f"(c[2]), "+f"(c[3])
        : "r"(a[0]), "r"(a[1]), "r"(a[2]), "r"(a[3]), "r"(b0), "r"(b1));
}
__device__ __forceinline__ void pack_k16(const float* v, uint32_t* w) {
    #pragma unroll
    for (int j = 0; j < 8; j++) {
        int p = (j & 1) ? (4 + (j >> 1)) : (j >> 1);
        __half2 h = __floats2half2_rn(v[2*p], v[2*p+1]);
        w[j] = *(uint32_t*)&h;
    }
}
__device__ __forceinline__ void ldrow16(float* v, const float* p, int lane) {
    const float4* p4 = (const float4*)(p + lane * 16);
    #pragma unroll
    for (int i = 0; i < 4; i++) {
        float4 t = p4[i];
        v[i*4+0] = t.x; v[i*4+1] = t.y; v[i*4+2] = t.z; v[i*4+3] = t.w;
    }
}

// ---------------- 0a. E -> fp16 permuted ----------------
__global__ void k_conv_E(const float* __restrict__ E) {
    int idx = blockIdx.x * blockDim.x + threadIdx.x;
    int n = idx >> 5, blk = idx & 31;
    const float* src = E + (size_t)n * DD + blk * 16;
    float v[16];
    #pragma unroll
    for (int i = 0; i < 4; i++) {
        float4 t = *(const float4*)(src + i * 4);
        v[i*4+0] = t.x; v[i*4+1] = t.y; v[i*4+2] = t.z; v[i*4+3] = t.w;
    }
    uint32_t w[8];
    pack_k16(v, w);
    uint4* dst = (uint4*)((char*)g_Eh + ((size_t)n * DD + blk * 16) * 2);
    dst[0] = make_uint4(w[0], w[1], w[2], w[3]);
    dst[1] = make_uint4(w[4], w[5], w[6], w[7]);
}

// ---------------- 0b. W -> transposed fp16 permuted ----------------
__global__ void k_conv_W(const float* __restrict__ Wih, const float* __restrict__ W1,
                         const float* __restrict__ W2) {
    int t = blockIdx.x * blockDim.x + threadIdx.x;
    int z = t / (DD * 32);
    int rem = t % (DD * 32);
    int n = rem >> 5, blk = rem & 31;
    const float* W = (z == 0) ? Wih : (z == 1) ? W1 : W2;
    float v[16];
    #pragma unroll
    for (int kk = 0; kk < 16; kk++)
        v[kk] = W[(size_t)(blk * 16 + kk) * DD + n];
    uint32_t w[8];
    pack_k16(v, w);
    uint4* dst = (uint4*)((char*)g_Wh + (((size_t)z * DD + n) * DD + blk * 16) * 2);
    dst[0] = make_uint4(w[0], w[1], w[2], w[3]);
    dst[1] = make_uint4(w[4], w[5], w[6], w[7]);
}

// ---------------- 1. embedding gather -> fp16 permuted ----------------
__global__ void k_gather(const int* __restrict__ tokens, const float* __restrict__ E) {
    int row = blockIdx.x * 8 + (threadIdx.x >> 5);
    int lane = threadIdx.x & 31;
    int tok = tokens[row];
    const float* src = E + (size_t)tok * DD + lane * 16;
    float v[16];
    #pragma unroll
    for (int i = 0; i < 4; i++) {
        float4 t = *(const float4*)(src + i * 4);
        v[i*4+0] = t.x; v[i*4+1] = t.y; v[i*4+2] = t.z; v[i*4+3] = t.w;
    }
    uint32_t w[8];
    pack_k16(v, w);
    uint4* dst = (uint4*)((char*)g_embh + ((size_t)row * DD + lane * 16) * 2);
    dst[0] = make_uint4(w[0], w[1], w[2], w[3]);
    dst[1] = make_uint4(w[4], w[5], w[6], w[7]);
}

// ---------------- 2. phase-1 GEMMs via fp16 mma (fused 3x) ----------------
#define STAGE_BYTES 32768
#define SMEM_MMA (3*STAGE_BYTES)
#define NCHUNK 8

__global__ __launch_bounds__(256, 2) void k_p1_mma(
    const float* __restrict__ bh, const float* __restrict__ b1f,
    const float* __restrict__ b2f)
{
    extern __shared__ char smem[];
    const uint32_t sb = smem_u32(smem);
    const int tid = threadIdx.x;
    const int wid = tid >> 5, lane = tid & 31;
    const int g = lane >> 2, t = lane & 3;
    const int warpM = wid >> 2, warpN = wid & 3;
    const int m0 = blockIdx.y * 128;
    const int z = blockIdx.x >> 2;
    const int nloc0 = (blockIdx.x & 3) * 128;
    const float* bias = (z == 0) ? bh : (z == 1) ? b1f : b2f;
    float* Out = (z == 0) ? g_f : (z == 1) ? g_x : g_t;

    float acc[4][4][4];
    #pragma unroll
    for (int mt = 0; mt < 4; mt++)
        #pragma unroll
        for (int nt = 0; nt < 4; nt++)
            #pragma unroll
            for (int i = 0; i < 4; i++) acc[mt][nt][i] = 0.f;

    const char* gA = (const char*)g_embh + (size_t)m0 * DD * 2;
    const char* gB = (const char*)g_Wh + ((size_t)z * DD + nloc0) * DD * 2;

    auto LOAD = [&](int c) {
        uint32_t st = sb + (uint32_t)(c % 3) * STAGE_BYTES;
        int kb = c * 128;
        #pragma unroll
        for (int it = 0; it < 4; it++) {
            int idx = it * 256 + tid;
            int row = idx >> 3, q = idx & 7;
            uint32_t so = swz((uint32_t)(row * 128 + q * 16));
            cp16(st + so,         gA + (size_t)row * 1024 + kb + q * 16);
            cp16(st + 16384 + so, gB + (size_t)row * 1024 + kb + q * 16);
        }
        cpcommit();
    };
    auto COMP = [&](int buf) {
        const char* sA = smem + buf * STAGE_BYTES;
        const char* sB = smem + buf * STAGE_BYTES + 16384;
        #pragma unroll
        for (int kk = 0; kk < 4; kk++) {
            uint32_t a[4][4];
            #pragma unroll
            for (int mt = 0; mt < 4; mt++) {
                int r0 = warpM * 64 + mt * 16 + g;
                uint2 v1 = *(const uint2*)(sA + swz((uint32_t)(r0 * 128 + kk * 32 + t * 8)));
                uint2 v2 = *(const uint2*)(sA + swz((uint32_t)((r0 + 8) * 128 + kk * 32 + t * 8)));
                a[mt][0] = v1.x; a[mt][1] = v2.x; a[mt][2] = v1.y; a[mt][3] = v2.y;
            }
            #pragma unroll
            for (int nt = 0; nt < 4; nt++) {
                int nr = warpN * 32 + nt * 8 + g;
                uint2 bv = *(const uint2*)(sB + swz((uint32_t)(nr * 128 + kk * 32 + t * 8)));
                #pragma unroll
                for (int mt = 0; mt < 4; mt++)
                    mma16816(acc[mt][nt], a[mt], bv.x, bv.y);
            }
        }
    };

    LOAD(0); LOAD(1);
    #pragma unroll 1
    for (int c = 0; c < NCHUNK; c++) {
        if (c < NCHUNK - 1) cpwait<1>(); else cpwait<0>();
        __syncthreads();
        if (c + 2 < NCHUNK) LOAD(c + 2);
        COMP(c % 3);
    }

    #pragma unroll
    for (int mt = 0; mt < 4; mt++) {
        int mrow = m0 + warpM * 64 + mt * 16 + g;
        #pragma unroll
        for (int nt = 0; nt < 4; nt++) {
            int nl = nloc0 + warpN * 32 + nt * 8 + 2 * t;
            float bx = bias[nl], by = bias[nl + 1];
            float2 lo, hi;
            lo.x = acc[mt][nt][0] + bx; lo.y = acc[mt][nt][1] + by;
            hi.x = acc[mt][nt][2] + bx; hi.y = acc[mt][nt][3] + by;
            if (z == 0) {
                lo.x = 1.f/(1.f+expf(-lo.x)); lo.y = 1.f/(1.f+expf(-lo.y));
                hi.x = 1.f/(1.f+expf(-hi.x)); hi.y = 1.f/(1.f+expf(-hi.y));
            }
            *(float2*)(Out + (size_t)mrow * DD + nl) = lo;
            *(float2*)(Out + (size_t)(mrow + 8) * DD + nl) = hi;
        }
    }
}

// ---------------- 3. combine + counter reset ----------------
__global__ void k_combine() {
    if (blockIdx.x == 0) {
        if (threadIdx.x < BB) { g_prog[threadIdx.x] = 0; g_scansm[threadIdx.x] = -1; }
        if (threadIdx.x == BB) g_tick = 0;
    }
    size_t i = (size_t)blockIdx.x * blockDim.x + threadIdx.x;
    float4 z1 = ((const float4*)g_x)[i];
    float4 z2 = ((const float4*)g_t)[i];
    float4 r;
    r.x = (z1.x / (1.f + expf(-z1.x))) * z2.x;
    r.y = (z1.y / (1.f + expf(-z1.y))) * z2.y;
    r.z = (z1.z / (1.f + expf(-z1.z))) * z2.z;
    r.w = (z1.w / (1.f + expf(-z1.w))) * z2.w;
    ((float4*)g_x)[i] = r;
}

// ---------------- 4. fused persistent kernel ----------------
__global__ __launch_bounds__(256, 2) void k_fused(
    float* __restrict__ out,
    const float* __restrict__ h0,
    const float* __restrict__ lng, const float* __restrict__ lnb,
    const float* __restrict__ lnfg, const float* __restrict__ lnfb)
{
    extern __shared__ char smem[];
    const int tid = threadIdx.x;
    const int wid = tid >> 5, lane = tid & 31;
    uint32_t mysm;
    asm("mov.u32 %0, %%smid;" : "=r"(mysm));

    if (blockIdx.x < BB) {
        // ================= scan CTA for batch b (identical to R10) =================
        float* ring = (float*)smem;
        volatile int* prog = (volatile int*)(smem + 32768);
        const int b = blockIdx.x;
        if (tid == 0) atomicExch(&g_scansm[b], (int)mysm);
        if (tid < 16) prog[tid] = 0;
        __syncthreads();

        if (wid == 7) {
            size_t base = (size_t)b * SS * DD;
            auto issue = [&](int s) {
                if (s < SS) {
                    uint32_t dst = smem_u32(ring + (size_t)(s & 7) * 1024);
                    const float* fs = g_f + base + (size_t)s * DD;
                    const float* xs = g_x + base + (size_t)s * DD;
                    #pragma unroll
                    for (int i = 0; i < 4; i++) {
                        int c = i * 32 + lane;
                        cp16(dst + c * 16,        fs + c * 4);
                        cp16(dst + 2048 + c * 16, xs + c * 4);
                    }
                }
                cpcommit();
            };
            #pragma unroll
            for (int p = 0; p < 6; p++) issue(p);

            float h[16], gw[16], gb[16];
            #pragma unroll
            for (int i = 0; i < 4; i++) {
                int off = i * 128 + lane * 4;
                *(float4*)(h  + i*4) = *(const float4*)(h0  + off);
                *(float4*)(gw + i*4) = *(const float4*)(lng + off);
                *(float4*)(gb + i*4) = *(const float4*)(lnb + off);
            }

            cpwait<5>();
            float fc[16], Bv[16];
            #pragma unroll
            for (int i = 0; i < 4; i++) {
                int off = i * 128 + lane * 4;
                float4 fv = *(const float4*)(ring + off);
                float4 xv = *(const float4*)(ring + 512 + off);
                fc[i*4+0]=fv.x; fc[i*4+1]=fv.y; fc[i*4+2]=fv.z; fc[i*4+3]=fv.w;
                Bv[i*4+0]=fmaf(-fv.x,xv.x,xv.x); Bv[i*4+1]=fmaf(-fv.y,xv.y,xv.y);
                Bv[i*4+2]=fmaf(-fv.z,xv.z,xv.z); Bv[i*4+3]=fmaf(-fv.w,xv.w,xv.w);
            }

            #pragma unroll 1
            for (int s = 0; s < SS; s++) {
                float hr[16];
                #pragma unroll
                for (int j = 0; j < 16; j++) hr[j] = fmaf(fc[j], h[j], Bv[j]);

                float p4s[4] = {0,0,0,0}, q4s[4] = {0,0,0,0};
                #pragma unroll
                for (int j = 0; j < 16; j++) {
                    p4s[j & 3] += hr[j];
                    q4s[j & 3] = fmaf(hr[j], hr[j], q4s[j & 3]);
                }
                float sum = (p4s[0] + p4s[1]) + (p4s[2] + p4s[3]);
                float ssq = (q4s[0] + q4s[1]) + (q4s[2] + q4s[3]);
                #pragma unroll
                for (int o = 16; o; o >>= 1) {
                    sum += __shfl_xor_sync(0xffffffffu, sum, o);
                    ssq += __shfl_xor_sync(0xffffffffu, ssq, o);
                }

                issue(s + 6);
                cpwait<5>();
                if (s + 1 < SS) {
                    const float* rg = ring + (size_t)((s + 1) & 7) * 1024;
                    #pragma unroll
                    for (int i = 0; i < 4; i++) {
                        int off = i * 128 + lane * 4;
                        float4 fv = *(const float4*)(rg + off);
                        float4 xv = *(const float4*)(rg + 512 + off);
                        fc[i*4+0]=fv.x; fc[i*4+1]=fv.y; fc[i*4+2]=fv.z; fc[i*4+3]=fv.w;
                        Bv[i*4+0]=fmaf(-fv.x,xv.x,xv.x); Bv[i*4+1]=fmaf(-fv.y,xv.y,xv.y);
                        Bv[i*4+2]=fmaf(-fv.z,xv.z,xv.z); Bv[i*4+3]=fmaf(-fv.w,xv.w,xv.w);
                    }
                }

                float mean = sum * (1.f / DD);
                float var  = fmaf(-mean, mean, ssq * (1.f / DD));
                float rstd = rsqrtf(var + EPSV);
                float t1   = -mean * rstd;
                #pragma unroll
                for (int j = 0; j < 16; j++)
                    h[j] = fmaf(gw[j], fmaf(hr[j], rstd, t1), gb[j] + h[j]);

                float* dst = g_xn + base + (size_t)s * DD;
                #pragma unroll
                for (int i = 0; i < 4; i++)
                    *(float4*)(dst + i * 128 + lane * 4) = *(float4*)(h + i * 4);

                if ((s & 7) == 7) {
                    __threadfence_block();
                    if (lane == 0) prog[0] = s + 1;
                }
            }
        } else {
            float gwf[16], gbf[16];
            ldrow16(gwf, lnfg, lane);
            ldrow16(gbf, lnfb, lane);
            const int slot = wid + 1;
            for (int r = wid; r < SS; r += 7) {
                if (lane == 0) { while (prog[0] <= r) __nanosleep(40); }
                __syncwarp();
                __threadfence_block();
                const float* p = g_xn + ((size_t)b * SS + r) * DD;
                float v[16];
                ldrow16(v, p, lane);
                float s4[4] = {0,0,0,0}, q4[4] = {0,0,0,0};
                #pragma unroll
                for (int j = 0; j < 16; j++) {
                    s4[j & 3] += v[j];
                    q4[j & 3] = fmaf(v[j], v[j], q4[j & 3]);
                }
                float sum = warp_sum((s4[0] + s4[1]) + (s4[2] + s4[3]));
                float ssq = warp_sum((q4[0] + q4[1]) + (q4[2] + q4[3]));
                float mean = sum * (1.f / DD);
                float var  = ssq * (1.f / DD) - mean * mean;
                float rstd = rsqrtf(var + EPSV);
                #pragma unroll
                for (int j = 0; j < 16; j++)
                    v[j] = fmaf((v[j] - mean) * rstd, gwf[j], gbf[j]);
                uint32_t w[8];
                pack_k16(v, w);
                uint4* dst = (uint4*)((char*)g_xh + (((size_t)b * SS + r) * DD + lane * 16) * 2);
                dst[0] = make_uint4(w[0], w[1], w[2], w[3]);
                dst[1] = make_uint4(w[4], w[5], w[6], w[7]);
                __threadfence();
                if (lane == 0) {
                    prog[slot] = r + 1;
                    int m = prog[1];
                    #pragma unroll
                    for (int i = 2; i < 8; i++) { int pv = prog[i]; m = (pv < m) ? pv : m; }
                    int k = m >> 7;
                    if (k > 0) atomicMax(&g_prog[b], k);
                }
                __syncwarp();
            }
            __threadfence();
            if (lane == 0) {
                prog[slot] = SS;
                int m = prog[1];
                #pragma unroll
                for (int i = 2; i < 8; i++) { int pv = prog[i]; m = (pv < m) ? pv : m; }
                atomicMax(&g_prog[b], m >> 7);
            }
        }
        return;
    }

    // ================= persistent logits worker =================
    __shared__ int s_t;
    __shared__ int s_evict;
    if (tid == 0) {
        int ev = 0;
        #pragma unroll 1
        for (int i = 0; i < BB; i++) {
            int v;
            do { v = atomicAdd(&g_scansm[i], 0); if (v < 0) __nanosleep(20); } while (v < 0);
            if ((uint32_t)v == mysm) ev = 1;
        }
        s_evict = ev;
    }
    __syncthreads();
    if (s_evict) return;

    const uint32_t sb = smem_u32(smem);
    const int g = lane >> 2, t = lane & 3;
    const int warpM = wid >> 2, warpN = wid & 3;

    // ---- hoisted fragment offsets: addr(kk) = base ^ (kk<<5) ----
    uint32_t aOff[4][2], bOff[4];
    #pragma unroll
    for (int mt = 0; mt < 4; mt++) {
        int r0 = warpM * 64 + mt * 16 + g;
        aOff[mt][0] = swz((uint32_t)(r0 * 128 + t * 8));
        aOff[mt][1] = swz((uint32_t)((r0 + 8) * 128 + t * 8));
    }
    #pragma unroll
    for (int nt = 0; nt < 4; nt++) {
        int nr = warpN * 32 + nt * 8 + g;
        bOff[nt] = 16384u + swz((uint32_t)(nr * 128 + t * 8));
    }
    // ---- hoisted loader offsets ----
    uint32_t ldSo[4]; int ldGo[4];
    #pragma unroll
    for (int it = 0; it < 4; it++) {
        int idx = it * 256 + tid;
        int row = idx >> 3, qb = (idx & 7) * 16;
        ldSo[it] = swz((uint32_t)(row * 128 + qb));
        ldGo[it] = row * 1024 + qb;
    }

    auto LOADT = [&](int c, const char* gA, const char* gB) {
        uint32_t st = sb + (uint32_t)(c % 3) * STAGE_BYTES;
        int kb = c * 128;
        #pragma unroll
        for (int it = 0; it < 4; it++) {
            cp16(st + ldSo[it],          gA + (size_t)(ldGo[it] + kb));
            cp16(st + 16384 + ldSo[it],  gB + (size_t)(ldGo[it] + kb));
        }
        cpcommit();
    };

    float acc[4][4][4];
    auto COMPT = [&](int buf) {
        const char* sBase = smem + buf * STAGE_BYTES;
        #pragma unroll
        for (int kk = 0; kk < 4; kk++) {
            const uint32_t kx = (uint32_t)kk << 5;
            uint32_t a[4][4];
            #pragma unroll
            for (int mt = 0; mt < 4; mt++) {
                uint2 v1 = *(const uint2*)(sBase + (aOff[mt][0] ^ kx));
                uint2 v2 = *(const uint2*)(sBase + (aOff[mt][1] ^ kx));
                a[mt][0] = v1.x; a[mt][1] = v2.x; a[mt][2] = v1.y; a[mt][3] = v2.y;
            }
            #pragma unroll
            for (int nt = 0; nt < 4; nt++) {
                uint2 bv = *(const uint2*)(sBase + (bOff[nt] ^ kx));
                #pragma unroll
                for (int mt = 0; mt < 4; mt++)
                    mma16816(acc[mt][nt], a[mt], bv.x, bv.y);
            }
        }
    };

    // decode + gate + issue first 2 chunks for a ticket
    int m0, n0;
    const char *gA, *gB;
    auto PREP = [&](int tk) {
        int seg = tk / (NTILE_N * BB);
        int rem = tk % (NTILE_N * BB);
        int b = rem & 7;
        n0 = (rem >> 3) * 128;
        if (tid == 0) {
            int p;
            for (;;) {
                asm volatile("ld.global.acquire.gpu.s32 %0, [%1];" : "=r"(p) : "l"(&g_prog[b]));
                if (p > seg) break;
                __nanosleep(60);
            }
        }
        __syncthreads();
        m0 = b * SS + seg * SEGLEN;
        gA = (const char*)g_xh + (size_t)m0 * DD * 2;
        gB = (const char*)g_Eh + (size_t)n0 * DD * 2;
        LOADT(0, gA, gB);
        LOADT(1, gA, gB);
    };

    if (tid == 0) s_t = atomicAdd(&g_tick, 1);
    __syncthreads();
    int tkt = s_t;
    if (tkt >= NTILES) return;
    PREP(tkt);

    #pragma unroll 1
    while (tkt < NTILES) {
        #pragma unroll
        for (int mt = 0; mt < 4; mt++)
            #pragma unroll
            for (int nt = 0; nt < 4; nt++)
                #pragma unroll
                for (int i = 0; i < 4; i++) acc[mt][nt][i] = 0.f;

        const char* cgA = gA;
        const char* cgB = gB;
        const int cm0 = m0, cn0 = n0;

        #pragma unroll 1
        for (int c = 0; c < NCHUNK; c++) {
            if (c < NCHUNK - 1) cpwait<1>(); else cpwait<0>();
            __syncthreads();
            if (c + 2 < NCHUNK) LOADT(c + 2, cgA, cgB);
            COMPT(c % 3);
        }

        // fetch next ticket + prefetch its first chunks BEFORE the epilogue
        if (tid == 0) s_t = atomicAdd(&g_tick, 1);
        __syncthreads();                 // also guards stage 0/1 reuse
        int ntkt = s_t;
        if (ntkt < NTILES) PREP(ntkt);

        // epilogue for current tile (overlaps next tile's cp.async fill)
        #pragma unroll
        for (int mt = 0; mt < 4; mt++) {
            int mrow = cm0 + warpM * 64 + mt * 16 + g;
            #pragma unroll
            for (int nt = 0; nt < 4; nt++) {
                int ncol = cn0 + warpN * 32 + nt * 8 + 2 * t;
                float2 lo; lo.x = acc[mt][nt][0]; lo.y = acc[mt][nt][1];
                float2 hi; hi.x = acc[mt][nt][2]; hi.y = acc[mt][nt][3];
                *(float2*)(out + (size_t)mrow * VV + ncol) = lo;
                *(float2*)(out + (size_t)(mrow + 8) * VV + ncol) = hi;
            }
        }
        tkt = ntkt;
    }
}

// ---------------- launch ----------------
extern "C" void kernel_launch(void* const* d_in, const int* in_sizes, int n_in,
                              void* d_out, int out_size) {
    const int*   tokens = (const int*)  d_in[0];
    const float* E      = (const float*)d_in[1];
    const float* W_ih   = (const float*)d_in[2];
    const float* b_h    = (const float*)d_in[3];
    const float* W1     = (const float*)d_in[4];
    const float* b1     = (const float*)d_in[5];
    const float* W2     = (const float*)d_in[6];
    const float* b2     = (const float*)d_in[7];
    const float* ln_g   = (const float*)d_in[8];
    const float* ln_b   = (const float*)d_in[9];
    const float* h0     = (const float*)d_in[10];
    const float* lnf_g  = (const float*)d_in[11];
    const float* lnf_b  = (const float*)d_in[12];
    float* out = (float*)d_out;

    static int init_done = 0;
    if (!init_done) {
        cudaFuncSetAttribute(k_p1_mma, cudaFuncAttributeMaxDynamicSharedMemorySize, SMEM_MMA);
        cudaFuncSetAttribute(k_fused,  cudaFuncAttributeMaxDynamicSharedMemorySize, SMEM_MMA);
        init_done = 1;
    }

    k_conv_E<<<(VV*32)/256, 256>>>(E);
    k_conv_W<<<(3*DD*32)/256, 256>>>(W_ih, W1, W2);
    k_gather<<<BSZ/8, 256>>>(tokens, E);
    k_p1_mma<<<dim3(12, 64), 256, SMEM_MMA>>>(b_h, b1, b2);
    k_combine<<<4096, 256>>>();
    k_fused<<<BB + 288, 256, SMEM_MMA>>>(out, h0, ln_g, ln_b, lnf_g, lnf_b);
}